// round 15
// baseline (speedup 1.0000x reference)
#include <cuda_runtime.h>
#include <cuda_bf16.h>
#include <cstdint>

// Problem constants
#define NN      29040        // nodes (121*240)
#define EE      464640       // edges (NN*16)
#define HH      128          // hidden
#define LVV     11           // levels
#define NLAT    121
#define NLON    240

// Edge kernel tiling
#define ETILE   128
#define ETHREADS 512
#define SI_STR  36           // w_diff(33)+attr(1), padded
#define SB_STR  132          // padded 128 (fp32 buffers, node/pq kernels)
#define AK      136          // bf16 activation row stride (conflict-free for LDSM)
#define WK      136          // bf16 weight row stride
#define PF_STR  136          // f32 stride of the unioned weight/PQ/c1 buffer

// Node kernel tiling
#define NTILE   32
#define NA_STR  384          // 3*H

typedef unsigned long long u64;

// ---- packed f32x2 helpers ----
__device__ __forceinline__ u64 pk2(float lo, float hi) {
    u64 r; asm("mov.b64 %0, {%1,%2};" : "=l"(r) : "f"(lo), "f"(hi)); return r;
}
__device__ __forceinline__ void ffma2(u64& acc, u64 a, u64 b) {
    asm("fma.rn.f32x2 %0, %1, %2, %0;" : "+l"(acc) : "l"(a), "l"(b));
}
__device__ __forceinline__ float hadd2(u64 x) {
    float lo, hi; asm("mov.b64 {%0,%1}, %2;" : "=f"(lo), "=f"(hi) : "l"(x));
    return lo + hi;
}

// ---- bf16 split helpers ----
__device__ __forceinline__ void bf16split(float x, __nv_bfloat16& hi, __nv_bfloat16& lo) {
    hi = __float2bfloat16_rn(x);
    lo = __float2bfloat16_rn(x - __bfloat162float(hi));
}

// ---- m16n8k16 bf16 MMA ----
__device__ __forceinline__ void mma16816(float* c,
    uint32_t a0, uint32_t a1, uint32_t a2, uint32_t a3,
    uint32_t b0, uint32_t b1)
{
    asm volatile(
        "mma.sync.aligned.m16n8k16.row.col.f32.bf16.bf16.f32 "
        "{%0,%1,%2,%3}, {%4,%5,%6,%7}, {%8,%9}, {%0,%1,%2,%3};"
        : "+f"(c[0]), "+f"(c[1]), "+f"(c[2]), "+f"(c[3])
        : "r"(a0), "r"(a1), "r"(a2), "r"(a3), "r"(b0), "r"(b1));
}

// ---- ldmatrix x4 ----
__device__ __forceinline__ void ldsm4(uint32_t* r, uint32_t addr) {
    asm volatile("ldmatrix.sync.aligned.m8n8.x4.shared.b16 {%0,%1,%2,%3}, [%4];"
                 : "=r"(r[0]), "=r"(r[1]), "=r"(r[2]), "=r"(r[3]) : "r"(addr));
}

// ---- scratch ----
__device__ float g_agg[NN * HH];
__device__ float g_wind[NN * 22];
__device__ float g_cnt[NN];
__device__ float g_lat[NLAT * HH];
__device__ float g_PQ[NN * 256];
__device__ __align__(16) __nv_bfloat16 g_We2hi[HH * WK];
__device__ __align__(16) __nv_bfloat16 g_We2lo[HH * WK];
__device__ __align__(16) __nv_bfloat16 g_Wc1hi[HH * WK];
__device__ __align__(16) __nv_bfloat16 g_Wc1lo[HH * WK];

// ---- edge-kernel SMEM layout (byte offsets) ----
// The W region (sWhi+sWlo, 69632 B) is time-multiplexed:
//   setup..GEMM1 : fp32 PQ      [128][PF_STR]
//   GEMM2        : We2 bf16 hi/lo
//   coordGEMM1   : Wc1 bf16 hi/lo
//   coordGEMM2   : fp32 c1      [128][PF_STR]
#define OFF_UNION 0
#define SZ_UNION  (ETILE*SI_STR*4)            // 18432 >= 64*22*8 (sIn / sWcl)
#define OFF_ROW   (OFF_UNION + SZ_UNION)      // 18432
#define OFF_RAD   (OFF_ROW + ETILE*4)         // 18944
#define OFF_AHI   (OFF_RAD + ETILE*2*4)       // 19968
#define OFF_ALO   (OFF_AHI + ETILE*AK*2)      // 54784
#define OFF_WHI   (OFF_ALO + ETILE*AK*2)      // 89600
#define OFF_WLO   (OFF_WHI + HH*WK*2)         // 124416
#define EDGE_SMEM (OFF_WLO + HH*WK*2)         // 159232 bytes
// static check: fp32 union buffer fits exactly in the W region
static_assert(ETILE * PF_STR * 4 == 2 * HH * WK * 2, "W region size mismatch");

// ============================================================
__global__ void zero_kernel() {
    int i = blockIdx.x * 256 + threadIdx.x;
    if (i < NN * HH) g_agg[i] = 0.f;
    if (i < NN * 22) g_wind[i] = 0.f;
    if (i < NN)      g_cnt[i] = 0.f;
}

// ============================================================
__global__ void wsplit_kernel(const float* __restrict__ We2,
                              const float* __restrict__ Wc1)
{
    int idx = blockIdx.x * 256 + threadIdx.x;
    if (idx >= 2 * HH * HH) return;
    int w = idx >> 14, r = idx & (HH * HH - 1);
    int k = r >> 7, n = r & 127;
    float x = (w ? Wc1 : We2)[k * HH + n];
    __nv_bfloat16 hi, lo; bf16split(x, hi, lo);
    if (w) { g_Wc1hi[n * WK + k] = hi; g_Wc1lo[n * WK + k] = lo; }
    else   { g_We2hi[n * WK + k] = hi; g_We2lo[n * WK + k] = lo; }
}

// ============================================================
// Precompute P = h @ W_e1[0:128,:], Q = h @ W_e1[128:256,:]
__global__ __launch_bounds__(256, 2)
void pq_kernel(const float* __restrict__ h,
               const float* __restrict__ W_e1)
{
    extern __shared__ __align__(16) float smemf[];
    float* sH = smemf;                 // [64][SB_STR]

    const int tid = threadIdx.x;
    const int n0  = blockIdx.x * 64;

    {
        int e = tid >> 2, sub = tid & 3;
        int n = n0 + e;
        float4* dst = (float4*)(sH + e * SB_STR);
        if (n < NN) {
            const float4* hh = (const float4*)(h + (size_t)n * HH);
            #pragma unroll
            for (int i = 0; i < 8; i++) dst[sub + 4*i] = hh[sub + 4*i];
        } else {
            float4 z = make_float4(0.f,0.f,0.f,0.f);
            #pragma unroll
            for (int i = 0; i < 8; i++) dst[sub + 4*i] = z;
        }
    }
    __syncthreads();

    const int j  = tid & 127;
    const int eg = tid >> 7;

    #pragma unroll
    for (int half = 0; half < 2; half++) {
        const float* W = W_e1 + half * 128 * HH;
        u64 acc[32];
        #pragma unroll
        for (int e = 0; e < 32; e++) acc[e] = 0ULL;
        const float* base = sH + (eg * 32) * SB_STR;
        for (int k = 0; k < 128; k += 4) {
            u64 W01 = pk2(W[(k+0)*HH + j], W[(k+1)*HH + j]);
            u64 W23 = pk2(W[(k+2)*HH + j], W[(k+3)*HH + j]);
            #pragma unroll
            for (int e = 0; e < 32; e++) {
                ulonglong2 a = *(const ulonglong2*)(base + e * SB_STR + k);
                ffma2(acc[e], a.x, W01);
                ffma2(acc[e], a.y, W23);
            }
        }
        #pragma unroll
        for (int e = 0; e < 32; e++) {
            int n = n0 + eg*32 + e;
            if (n < NN) g_PQ[(size_t)n * 256 + half * 128 + j] = hadd2(acc[e]);
        }
    }
}

// ============================================================
__device__ __forceinline__ void copy_weights(const __nv_bfloat16* __restrict__ ghi,
                                             const __nv_bfloat16* __restrict__ glo,
                                             __nv_bfloat16* sWhi, __nv_bfloat16* sWlo,
                                             int tid)
{
    const uint4* srcH = (const uint4*)ghi;
    const uint4* srcL = (const uint4*)glo;
    uint4* dstH = (uint4*)sWhi;
    uint4* dstL = (uint4*)sWlo;
    const int nvec = HH * WK * 2 / 16;    // 2176
    for (int i = tid; i < nvec; i += ETHREADS) {
        dstH[i] = srcH[i];
        dstL[i] = srcL[i];
    }
}

// MMA compute: 16 warps, warp w -> m-pair (w&3)*32, n-group (w>>2)*32.
// acc layout: acc[mb*16 + nb*4 + {r0c0,r0c1,r1c0,r1c1}]
__device__ __forceinline__ void mma_compute(float (&acc)[32],
    const __nv_bfloat16* __restrict__ sAhi, const __nv_bfloat16* __restrict__ sAlo,
    const __nv_bfloat16* __restrict__ sWhi, const __nv_bfloat16* __restrict__ sWlo,
    int tid)
{
    const int w = tid >> 5, lane = tid & 31;
    const int m0 = (w & 3) * 32;
    const int n0 = (w >> 2) * 32;

    #pragma unroll
    for (int i = 0; i < 32; i++) acc[i] = 0.f;

    const int arow = m0 + (lane & 15);
    const int akk  = (lane >> 4) << 3;
    uint32_t aAhi = (uint32_t)__cvta_generic_to_shared(sAhi + arow * AK + akk);
    uint32_t aAlo = (uint32_t)__cvta_generic_to_shared(sAlo + arow * AK + akk);
    const int brow = n0 + (lane & 7) + ((lane & 16) ? 8 : 0);
    const int bkk  = (lane & 8) ? 8 : 0;
    uint32_t aBhi = (uint32_t)__cvta_generic_to_shared(sWhi + brow * WK + bkk);
    uint32_t aBlo = (uint32_t)__cvta_generic_to_shared(sWlo + brow * WK + bkk);

    #pragma unroll
    for (int kb = 0; kb < 8; kb++) {
        uint32_t ah0[4], ah1[4], al0[4], al1[4];
        ldsm4(ah0, aAhi);
        ldsm4(ah1, aAhi + 16 * AK * 2);
        ldsm4(al0, aAlo);
        ldsm4(al1, aAlo + 16 * AK * 2);
        uint32_t bh0[4], bh1[4], bl0[4], bl1[4];
        ldsm4(bh0, aBhi);
        ldsm4(bh1, aBhi + 16 * WK * 2);
        ldsm4(bl0, aBlo);
        ldsm4(bl1, aBlo + 16 * WK * 2);

        #pragma unroll
        for (int mb = 0; mb < 2; mb++) {
            const uint32_t* ah = mb ? ah1 : ah0;
            const uint32_t* al = mb ? al1 : al0;
            #pragma unroll
            for (int nb = 0; nb < 4; nb++) {
                const uint32_t* bh = (nb < 2) ? bh0 : bh1;
                const uint32_t* bl = (nb < 2) ? bl0 : bl1;
                const int o = (nb & 1) * 2;
                float* c = acc + mb * 16 + nb * 4;
                mma16816(c, ah[0], ah[1], ah[2], ah[3], bh[o], bh[o+1]);
                mma16816(c, ah[0], ah[1], ah[2], ah[3], bl[o], bl[o+1]);
                mma16816(c, al[0], al[1], al[2], al[3], bh[o], bh[o+1]);
            }
        }
        aAhi += 32; aAlo += 32; aBhi += 32; aBlo += 32;   // 16 bf16 = 32 bytes
    }
}

// ============================================================
// Fused edge pass: 128 edges/tile, 512 threads
__global__ __launch_bounds__(ETHREADS, 1)
void edge_kernel(const float* __restrict__ u,
                 const float* __restrict__ v,
                 const float* __restrict__ edge_attr,
                 const float* __restrict__ W_e1, const float* __restrict__ b_e1,
                 const float* __restrict__ b_e2,
                 const float* __restrict__ b_c1,
                 const float* __restrict__ W_cl,
                 const int*   __restrict__ edge_index)
{
    extern __shared__ __align__(16) char smem[];
    float* sIn  = (float*)(smem + OFF_UNION);      // GEMM1 inputs (phase 1)
    u64*   sWcl = (u64*)  (smem + OFF_UNION);      // coordGEMM2 weights (phase 2)
    int*   sRow = (int*)  (smem + OFF_ROW);
    float* sRad = (float*)(smem + OFF_RAD);
    __nv_bfloat16* sAhi = (__nv_bfloat16*)(smem + OFF_AHI);
    __nv_bfloat16* sAlo = (__nv_bfloat16*)(smem + OFF_ALO);
    __nv_bfloat16* sWhi = (__nv_bfloat16*)(smem + OFF_WHI);
    __nv_bfloat16* sWlo = (__nv_bfloat16*)(smem + OFF_WLO);
    float* sWF = (float*)(smem + OFF_WHI);         // fp32 [128][PF_STR] union view

    const int tid = threadIdx.x;
    const int e0  = blockIdx.x * ETILE;

    // ---- setup: gather PQ as raw fp32 into the W-region; w_diff; rad2 ----
    {   // gather P[row]+Q[col] -> fp32 (no splits)
        int e = tid >> 2, sub = tid & 3;
        int gidx = e0 + e;
        int r = edge_index[gidx];
        int c = edge_index[EE + gidx];
        const float4* Pr = (const float4*)(g_PQ + (size_t)r * 256);
        const float4* Qc = (const float4*)(g_PQ + (size_t)c * 256 + 128);
        float4* dst = (float4*)(sWF + e * PF_STR);
        #pragma unroll
        for (int i = 0; i < 8; i++) {
            int f4 = sub + 4*i;
            float4 a = Pr[f4];
            float4 b = Qc[f4];
            dst[f4] = make_float4(a.x+b.x, a.y+b.y, a.z+b.z, a.w+b.w);
        }
        if (sub == 0) {
            sRow[e] = r;
            sIn[e * SI_STR + 33] = edge_attr[gidx];
            sIn[e * SI_STR + 34] = 0.f;
            sIn[e * SI_STR + 35] = 0.f;
            atomicAdd(&g_cnt[r], 1.0f);
        }
    }

    for (int idx = tid; idx < ETILE * LVV; idx += ETHREADS) {   // w_diff
        int e = idx / LVV, lv = idx - e * LVV;
        int gidx = e0 + e;
        int r = edge_index[gidx], c = edge_index[EE + gidx];
        float ucv = u[c * LVV + lv], vcv = v[c * LVV + lv];
        float urv = u[r * LVV + lv], vrv = v[r * LVV + lv];
        float cs = sqrtf(ucv * ucv + vcv * vcv);
        float rs = sqrtf(urv * urv + vrv * vrv);
        float rd = (ucv * urv + vcv * vrv) / (cs * rs);
        float* rrow = sIn + e * SI_STR;
        rrow[0  + lv] = rd;
        rrow[11 + lv] = cs;
        rrow[22 + lv] = rs;
    }

    for (int e = tid; e < ETILE; e += ETHREADS) {               // rad2
        int gidx = e0 + e;
        int c = edge_index[EE + gidx];
        float su = 0.f, sv = 0.f;
        #pragma unroll
        for (int lv = 0; lv < LVV; lv++) {
            float a = u[c * LVV + lv], b = v[c * LVV + lv];
            su += a * a; sv += b * b;
        }
        sRad[e * 2 + 0] = sqrtf(su);
        sRad[e * 2 + 1] = sqrtf(sv);
    }
    __syncthreads();

    const int j  = tid & 127;
    const int eg = tid >> 7;       // 0..3, 32 rows each

    // ---- GEMM1 (34-k scalar): hid = relu(PQ + w_diff@W_e1[256:] + b_e1)
    //      reads fp32 PQ, writes hid bf16 splits into sA ----
    {
        const float* W1w = W_e1 + 256 * HH;
        float bb = b_e1[j];
        float acc[32];
        #pragma unroll
        for (int e = 0; e < 32; e++)
            acc[e] = sWF[(eg * 32 + e) * PF_STR + j] + bb;
        const float* base = sIn + (eg * 32) * SI_STR;
        for (int k = 0; k < 32; k += 4) {
            float w0 = W1w[(k+0)*HH + j], w1 = W1w[(k+1)*HH + j];
            float w2 = W1w[(k+2)*HH + j], w3 = W1w[(k+3)*HH + j];
            #pragma unroll
            for (int e = 0; e < 32; e++) {
                float4 a = *(const float4*)(base + e * SI_STR + k);
                acc[e] += a.x*w0 + a.y*w1 + a.z*w2 + a.w*w3;
            }
        }
        {
            float w0 = W1w[32*HH + j], w1 = W1w[33*HH + j];
            #pragma unroll
            for (int e = 0; e < 32; e++) {
                const float* rr = base + e * SI_STR;
                acc[e] += rr[32]*w0 + rr[33]*w1;
            }
        }
        #pragma unroll
        for (int e = 0; e < 32; e++) {
            float hv = fmaxf(acc[e], 0.f);
            __nv_bfloat16 hi, lo; bf16split(hv, hi, lo);
            int row = eg * 32 + e;
            sAhi[row * AK + j] = hi;
            sAlo[row * AK + j] = lo;
        }
    }
    __syncthreads();   // PQ fp32 dead; hid splits ready

    // ---- load We2 weights into W-region (overwrites PQ); fill sWcl (overwrites sIn) ----
    copy_weights(g_We2hi, g_We2lo, sWhi, sWlo, tid);
    for (int idx = tid; idx < 64 * 22; idx += ETHREADS) {
        int kk = idx / 22, m = idx - kk * 22;
        sWcl[idx] = pk2(W_cl[(2*kk) * 22 + m], W_cl[(2*kk+1) * 22 + m]);
    }
    __syncthreads();

    // ---- GEMM2 (tensor): feat = relu(hid @ W_e2 + b_e2)
    //      epilogue: scatter to g_agg + write feat splits in place ----
    {
        float acc[32];
        mma_compute(acc, sAhi, sAlo, sWhi, sWlo, tid);
        __syncthreads();   // all MMA reads of sA (hid) / sW (We2) complete

        const int w = tid >> 5, lane = tid & 31;
        const int g = lane >> 2, tig = lane & 3;
        const int m0 = (w & 3) * 32;
        const int n0w = (w >> 2) * 32;
        #pragma unroll
        for (int mb = 0; mb < 2; mb++) {
            const int rA = m0 + mb * 16 + g;
            const int r0 = sRow[rA], r1 = sRow[rA + 8];
            #pragma unroll
            for (int nb = 0; nb < 4; nb++) {
                const int nn = n0w + nb * 8 + 2 * tig;
                const float* c = acc + mb * 16 + nb * 4;
                float b0 = b_e2[nn], b1 = b_e2[nn + 1];
                float v00 = fmaxf(c[0] + b0, 0.f);
                float v01 = fmaxf(c[1] + b1, 0.f);
                float v10 = fmaxf(c[2] + b0, 0.f);
                float v11 = fmaxf(c[3] + b1, 0.f);
                asm volatile("red.global.add.v2.f32 [%0], {%1,%2};"
                             :: "l"(g_agg + (size_t)r0 * HH + nn), "f"(v00), "f"(v01) : "memory");
                asm volatile("red.global.add.v2.f32 [%0], {%1,%2};"
                             :: "l"(g_agg + (size_t)r1 * HH + nn), "f"(v10), "f"(v11) : "memory");
                __nv_bfloat16 h0,l0,h1,l1;
                __nv_bfloat162 th, tl;
                bf16split(v00, h0, l0); bf16split(v01, h1, l1);
                th.x=h0; th.y=h1; tl.x=l0; tl.y=l1;
                *(__nv_bfloat162*)(sAhi + rA * AK + nn) = th;
                *(__nv_bfloat162*)(sAlo + rA * AK + nn) = tl;
                bf16split(v10, h0, l0); bf16split(v11, h1, l1);
                th.x=h0; th.y=h1; tl.x=l0; tl.y=l1;
                *(__nv_bfloat162*)(sAhi + (rA + 8) * AK + nn) = th;
                *(__nv_bfloat162*)(sAlo + (rA + 8) * AK + nn) = tl;
            }
        }
    }

    // ---- swap weights to W_c1 (We2 fully consumed before the sync above) ----
    copy_weights(g_Wc1hi, g_Wc1lo, sWhi, sWlo, tid);
    __syncthreads();

    // ---- coord GEMM1 (tensor): c1 = relu(feat @ W_c1 + b_c1),
    //      epilogue writes c1 as fp32 into the W-region (Wc1 now dead) ----
    {
        float acc[32];
        mma_compute(acc, sAhi, sAlo, sWhi, sWlo, tid);
        __syncthreads();   // all MMA reads of sA (feat) and sW (Wc1) complete

        const int w = tid >> 5, lane = tid & 31;
        const int g = lane >> 2, tig = lane & 3;
        const int m0 = (w & 3) * 32;
        const int n0w = (w >> 2) * 32;
        #pragma unroll
        for (int mb = 0; mb < 2; mb++) {
            const int rA = m0 + mb * 16 + g;
            #pragma unroll
            for (int nb = 0; nb < 4; nb++) {
                const int nn = n0w + nb * 8 + 2 * tig;
                const float* c = acc + mb * 16 + nb * 4;
                float b0 = b_c1[nn], b1 = b_c1[nn + 1];
                float2 p0 = make_float2(fmaxf(c[0] + b0, 0.f), fmaxf(c[1] + b1, 0.f));
                float2 p1 = make_float2(fmaxf(c[2] + b0, 0.f), fmaxf(c[3] + b1, 0.f));
                *(float2*)(sWF + rA * PF_STR + nn) = p0;
                *(float2*)(sWF + (rA + 8) * PF_STR + nn) = p1;
            }
        }
    }
    __syncthreads();

    // ---- coord GEMM2 (H->22, scalar fp32) * rad2, scatter wind ----
    for (int idx = tid; idx < ETILE * 22; idx += ETHREADS) {
        int e = idx / 22, m = idx - e * 22;
        const u64* brow = (const u64*)(sWF + e * PF_STR);   // 64 f32 k-pairs
        u64 acc = 0ULL;
        #pragma unroll 8
        for (int kk = 0; kk < 64; kk++)
            ffma2(acc, brow[kk], sWcl[kk * 22 + m]);
        float r2 = sRad[e * 2 + (m >= 11 ? 1 : 0)];
        atomicAdd(&g_wind[(size_t)sRow[e] * 22 + m], hadd2(acc) * r2);
    }
}

// ============================================================
__global__ void lat_kernel() {
    int lt = blockIdx.x;
    int jj = threadIdx.x;
    float s = 0.f;
    for (int lon = 0; lon < NLON; lon++)
        s += g_agg[((size_t)lt * NLON + lon) * HH + jj];
    g_lat[lt * HH + jj] = s * (1.0f / NLON);
}

// ============================================================
__global__ __launch_bounds__(256, 3)
void node_kernel(const float* __restrict__ h,
                 const float* __restrict__ W_n1, const float* __restrict__ b_n1,
                 const float* __restrict__ W_n2, const float* __restrict__ b_n2,
                 float* __restrict__ out)
{
    extern __shared__ __align__(16) float smemf[];
    float* sA = smemf;
    float* sB = sA + NTILE * NA_STR;

    const int tid = threadIdx.x;
    const int n0  = blockIdx.x * NTILE;

    {
        int e = tid >> 3, sub = tid & 7;
        int n = n0 + e;
        float4* dst = (float4*)(sA + e * NA_STR);
        if (n < NN) {
            const float4* hh = (const float4*)(h + (size_t)n * HH);
            const float4* aa = (const float4*)(g_agg + (size_t)n * HH);
            const float4* ll = (const float4*)(g_lat + (size_t)(n / NLON) * HH);
            #pragma unroll
            for (int i = 0; i < 4; i++) {
                dst[sub + 8*i]      = hh[sub + 8*i];
                dst[32 + sub + 8*i] = aa[sub + 8*i];
                dst[64 + sub + 8*i] = ll[sub + 8*i];
            }
        } else {
            float4 z = make_float4(0.f, 0.f, 0.f, 0.f);
            #pragma unroll
            for (int i = 0; i < 4; i++) {
                dst[sub + 8*i] = z; dst[32 + sub + 8*i] = z; dst[64 + sub + 8*i] = z;
            }
        }
    }
    __syncthreads();

    const int j  = tid & 127;
    const int eg = tid >> 7;

    {
        u64 acc[16];
        #pragma unroll
        for (int e = 0; e < 16; e++) acc[e] = 0ULL;
        const float* base = sA + (eg * 16) * NA_STR;
        for (int k = 0; k < NA_STR; k += 4) {
            u64 W01 = pk2(W_n1[(k+0)*HH + j], W_n1[(k+1)*HH + j]);
            u64 W23 = pk2(W_n1[(k+2)*HH + j], W_n1[(k+3)*HH + j]);
            #pragma unroll
            for (int e = 0; e < 16; e++) {
                ulonglong2 a = *(const ulonglong2*)(base + e * NA_STR + k);
                ffma2(acc[e], a.x, W01);
                ffma2(acc[e], a.y, W23);
            }
        }
        float bb = b_n1[j];
        #pragma unroll
        for (int e = 0; e < 16; e++)
            sB[(eg*16 + e)*SB_STR + j] = fmaxf(hadd2(acc[e]) + bb, 0.f);
    }
    __syncthreads();

    {
        u64 acc[16];
        #pragma unroll
        for (int e = 0; e < 16; e++) acc[e] = 0ULL;
        const float* base = sB + (eg * 16) * SB_STR;
        for (int k = 0; k < 128; k += 4) {
            u64 W01 = pk2(W_n2[(k+0)*HH + j], W_n2[(k+1)*HH + j]);
            u64 W23 = pk2(W_n2[(k+2)*HH + j], W_n2[(k+3)*HH + j]);
            #pragma unroll
            for (int e = 0; e < 16; e++) {
                ulonglong2 a = *(const ulonglong2*)(base + e * SB_STR + k);
                ffma2(acc[e], a.x, W01);
                ffma2(acc[e], a.y, W23);
            }
        }
        float bb = b_n2[j];
        #pragma unroll
        for (int e = 0; e < 16; e++) {
            int n = n0 + eg*16 + e;
            if (n < NN)
                out[(size_t)n * HH + j] = hadd2(acc[e]) + bb + h[(size_t)n * HH + j];
        }
    }
}

// ============================================================
__global__ void coord_kernel(float* __restrict__ out) {
    int i = blockIdx.x * 256 + threadIdx.x;
    if (i >= NN * 22) return;
    int n = i / 22, m = i - n * 22;
    float cnt = fmaxf(g_cnt[n], 1.0f);
    float val = g_wind[i] / cnt;
    val = fminf(fmaxf(val, -100.0f), 100.0f);
    int lv = (m >= 11) ? (m - 11) : m;
    float* o = out + (size_t)NN * HH + (m >= 11 ? NN * LVV : 0) + n * LVV + lv;
    *o = val;
}

// ============================================================
extern "C" void kernel_launch(void* const* d_in, const int* in_sizes, int n_in,
                              void* d_out, int out_size)
{
    const float* h         = (const float*)d_in[0];
    const float* u         = (const float*)d_in[1];
    const float* v         = (const float*)d_in[2];
    const float* edge_attr = (const float*)d_in[3];
    const float* W_e1      = (const float*)d_in[4];
    const float* b_e1      = (const float*)d_in[5];
    const float* W_e2      = (const float*)d_in[6];
    const float* b_e2      = (const float*)d_in[7];
    const float* W_n1      = (const float*)d_in[8];
    const float* b_n1      = (const float*)d_in[9];
    const float* W_n2      = (const float*)d_in[10];
    const float* b_n2      = (const float*)d_in[11];
    const float* W_c1      = (const float*)d_in[12];
    const float* b_c1      = (const float*)d_in[13];
    const float* W_cl      = (const float*)d_in[14];
    const int*   edge_index= (const int*)  d_in[15];
    float* out = (float*)d_out;

    const int PQ_SMEM   = 64 * SB_STR * 4;
    const int NODE_SMEM = (NTILE * NA_STR + NTILE * SB_STR) * 4;
    cudaFuncSetAttribute(pq_kernel,   cudaFuncAttributeMaxDynamicSharedMemorySize, PQ_SMEM);
    cudaFuncSetAttribute(edge_kernel, cudaFuncAttributeMaxDynamicSharedMemorySize, EDGE_SMEM);
    cudaFuncSetAttribute(node_kernel, cudaFuncAttributeMaxDynamicSharedMemorySize, NODE_SMEM);

    zero_kernel<<<(NN * HH + 255) / 256, 256>>>();
    wsplit_kernel<<<(2 * HH * HH + 255) / 256, 256>>>(W_e2, W_c1);

    pq_kernel<<<(NN + 63) / 64, 256, PQ_SMEM>>>(h, W_e1);

    edge_kernel<<<EE / ETILE, ETHREADS, EDGE_SMEM>>>(u, v, edge_attr,
                                                     W_e1, b_e1, b_e2,
                                                     b_c1, W_cl, edge_index);

    lat_kernel<<<NLAT, HH>>>();

    node_kernel<<<(NN + NTILE - 1) / NTILE, 256, NODE_SMEM>>>(h, W_n1, b_n1, W_n2, b_n2, out);

    coord_kernel<<<(NN * 22 + 255) / 256, 256>>>(out);
}

// round 17
// speedup vs baseline: 1.2704x; 1.2704x over previous
#include <cuda_runtime.h>
#include <cuda_bf16.h>
#include <cstdint>

// Problem constants
#define NN      29040        // nodes (121*240)
#define EE      464640       // edges (NN*16)
#define HH      128          // hidden
#define LVV     11           // levels
#define NLAT    121
#define NLON    240

// Edge kernel tiling
#define ETILE   128
#define ETHREADS 512
#define SI_STR  36           // w_diff(33)+attr(1), padded
#define SB_STR  132          // padded 128 (fp32 buffers, node/pq kernels)
#define AK      136          // bf16 activation row stride (conflict-free for LDSM)
#define WK      136          // bf16 weight row stride
#define PF_STR  136          // f32 stride of the unioned weight/PQ buffer
#define NCL     32           // padded N for the W_cl MMA (22 real)

// Node kernel tiling
#define NTILE   32
#define NA_STR  384          // 3*H

typedef unsigned long long u64;

// ---- packed f32x2 helpers ----
__device__ __forceinline__ u64 pk2(float lo, float hi) {
    u64 r; asm("mov.b64 %0, {%1,%2};" : "=l"(r) : "f"(lo), "f"(hi)); return r;
}
__device__ __forceinline__ void ffma2(u64& acc, u64 a, u64 b) {
    asm("fma.rn.f32x2 %0, %1, %2, %0;" : "+l"(acc) : "l"(a), "l"(b));
}
__device__ __forceinline__ float hadd2(u64 x) {
    float lo, hi; asm("mov.b64 {%0,%1}, %2;" : "=f"(lo), "=f"(hi) : "l"(x));
    return lo + hi;
}

// ---- bf16 split helpers ----
__device__ __forceinline__ void bf16split(float x, __nv_bfloat16& hi, __nv_bfloat16& lo) {
    hi = __float2bfloat16_rn(x);
    lo = __float2bfloat16_rn(x - __bfloat162float(hi));
}

// ---- m16n8k16 bf16 MMA ----
__device__ __forceinline__ void mma16816(float* c,
    uint32_t a0, uint32_t a1, uint32_t a2, uint32_t a3,
    uint32_t b0, uint32_t b1)
{
    asm volatile(
        "mma.sync.aligned.m16n8k16.row.col.f32.bf16.bf16.f32 "
        "{%0,%1,%2,%3}, {%4,%5,%6,%7}, {%8,%9}, {%0,%1,%2,%3};"
        : "+f"(c[0]), "+f"(c[1]), "+f"(c[2]), "+f"(c[3])
        : "r"(a0), "r"(a1), "r"(a2), "r"(a3), "r"(b0), "r"(b1));
}

// ---- ldmatrix x4 ----
__device__ __forceinline__ void ldsm4(uint32_t* r, uint32_t addr) {
    asm volatile("ldmatrix.sync.aligned.m8n8.x4.shared.b16 {%0,%1,%2,%3}, [%4];"
                 : "=r"(r[0]), "=r"(r[1]), "=r"(r[2]), "=r"(r[3]) : "r"(addr));
}

// ---- scratch ----
__device__ float g_agg[NN * HH];
__device__ float g_wind[NN * 22];
__device__ float g_cnt[NN];
__device__ float g_lat[NLAT * HH];
__device__ float g_PQ[NN * 256];
__device__ __align__(16) __nv_bfloat16 g_We2hi[HH * WK];
__device__ __align__(16) __nv_bfloat16 g_We2lo[HH * WK];
__device__ __align__(16) __nv_bfloat16 g_Wc1hi[HH * WK];
__device__ __align__(16) __nv_bfloat16 g_Wc1lo[HH * WK];
__device__ __align__(16) __nv_bfloat16 g_Wclhi[NCL * WK];   // [n][k], rows 22..31 zero
__device__ __align__(16) __nv_bfloat16 g_Wcllo[NCL * WK];

// ---- edge-kernel SMEM layout (byte offsets) ----
// W region (sWhi+sWlo, 69632 B) is time-multiplexed:
//   setup..GEMM1 : fp32 PQ [128][PF_STR]
//   GEMM2        : We2 bf16 hi/lo
//   coordGEMM1   : Wc1 bf16 hi/lo
// UNION region: sIn (GEMM1 inputs) then W_cl bf16 splits [32][WK] hi+lo.
#define OFF_UNION 0
#define SZ_UNION  (ETILE*SI_STR*4)            // 18432 >= 2*NCL*WK*2 = 17408
#define OFF_ROW   (OFF_UNION + SZ_UNION)      // 18432
#define OFF_RAD   (OFF_ROW + ETILE*4)         // 18944
#define OFF_AHI   (OFF_RAD + ETILE*2*4)       // 19968
#define OFF_ALO   (OFF_AHI + ETILE*AK*2)      // 54784
#define OFF_WHI   (OFF_ALO + ETILE*AK*2)      // 89600
#define OFF_WLO   (OFF_WHI + HH*WK*2)         // 124416
#define EDGE_SMEM (OFF_WLO + HH*WK*2)         // 159232 bytes
static_assert(ETILE * PF_STR * 4 == 2 * HH * WK * 2, "W region size mismatch");
static_assert(2 * NCL * WK * 2 <= SZ_UNION, "Wcl splits must fit UNION");

// ============================================================
__global__ void zero_kernel() {
    int i = blockIdx.x * 256 + threadIdx.x;
    if (i < NN * HH) g_agg[i] = 0.f;
    if (i < NN * 22) g_wind[i] = 0.f;
    if (i < NN)      g_cnt[i] = 0.f;
}

// ============================================================
// One-time weight splits: We2/Wc1 [k][n] -> hi/lo at [n*WK+k]; Wcl [k][22] -> [32][WK]
__global__ void wsplit_kernel(const float* __restrict__ We2,
                              const float* __restrict__ Wc1,
                              const float* __restrict__ Wcl)
{
    int idx = blockIdx.x * 256 + threadIdx.x;
    if (idx < 2 * HH * HH) {
        int w = idx >> 14, r = idx & (HH * HH - 1);
        int k = r >> 7, n = r & 127;
        float x = (w ? Wc1 : We2)[k * HH + n];
        __nv_bfloat16 hi, lo; bf16split(x, hi, lo);
        if (w) { g_Wc1hi[n * WK + k] = hi; g_Wc1lo[n * WK + k] = lo; }
        else   { g_We2hi[n * WK + k] = hi; g_We2lo[n * WK + k] = lo; }
    } else if (idx < 2 * HH * HH + NCL * HH) {
        int r = idx - 2 * HH * HH;
        int n = r >> 7, k = r & 127;
        float x = (n < 22) ? Wcl[k * 22 + n] : 0.f;
        __nv_bfloat16 hi, lo; bf16split(x, hi, lo);
        g_Wclhi[n * WK + k] = hi;
        g_Wcllo[n * WK + k] = lo;
    }
}

// ============================================================
// Precompute P = h @ W_e1[0:128,:], Q = h @ W_e1[128:256,:]
__global__ __launch_bounds__(256, 2)
void pq_kernel(const float* __restrict__ h,
               const float* __restrict__ W_e1)
{
    extern __shared__ __align__(16) float smemf[];
    float* sH = smemf;                 // [64][SB_STR]

    const int tid = threadIdx.x;
    const int n0  = blockIdx.x * 64;

    {
        int e = tid >> 2, sub = tid & 3;
        int n = n0 + e;
        float4* dst = (float4*)(sH + e * SB_STR);
        if (n < NN) {
            const float4* hh = (const float4*)(h + (size_t)n * HH);
            #pragma unroll
            for (int i = 0; i < 8; i++) dst[sub + 4*i] = hh[sub + 4*i];
        } else {
            float4 z = make_float4(0.f,0.f,0.f,0.f);
            #pragma unroll
            for (int i = 0; i < 8; i++) dst[sub + 4*i] = z;
        }
    }
    __syncthreads();

    const int j  = tid & 127;
    const int eg = tid >> 7;

    #pragma unroll
    for (int half = 0; half < 2; half++) {
        const float* W = W_e1 + half * 128 * HH;
        u64 acc[32];
        #pragma unroll
        for (int e = 0; e < 32; e++) acc[e] = 0ULL;
        const float* base = sH + (eg * 32) * SB_STR;
        for (int k = 0; k < 128; k += 4) {
            u64 W01 = pk2(W[(k+0)*HH + j], W[(k+1)*HH + j]);
            u64 W23 = pk2(W[(k+2)*HH + j], W[(k+3)*HH + j]);
            #pragma unroll
            for (int e = 0; e < 32; e++) {
                ulonglong2 a = *(const ulonglong2*)(base + e * SB_STR + k);
                ffma2(acc[e], a.x, W01);
                ffma2(acc[e], a.y, W23);
            }
        }
        #pragma unroll
        for (int e = 0; e < 32; e++) {
            int n = n0 + eg*32 + e;
            if (n < NN) g_PQ[(size_t)n * 256 + half * 128 + j] = hadd2(acc[e]);
        }
    }
}

// ============================================================
__device__ __forceinline__ void copy_weights(const __nv_bfloat16* __restrict__ ghi,
                                             const __nv_bfloat16* __restrict__ glo,
                                             __nv_bfloat16* sWhi, __nv_bfloat16* sWlo,
                                             int tid)
{
    const uint4* srcH = (const uint4*)ghi;
    const uint4* srcL = (const uint4*)glo;
    uint4* dstH = (uint4*)sWhi;
    uint4* dstL = (uint4*)sWlo;
    const int nvec = HH * WK * 2 / 16;    // 2176
    for (int i = tid; i < nvec; i += ETHREADS) {
        dstH[i] = srcH[i];
        dstL[i] = srcL[i];
    }
}

// MMA compute: 16 warps, warp w -> m-pair (w&3)*32, n-group (w>>2)*32.
// acc layout: acc[mb*16 + nb*4 + {r0c0,r0c1,r1c0,r1c1}]
__device__ __forceinline__ void mma_compute(float (&acc)[32],
    const __nv_bfloat16* __restrict__ sAhi, const __nv_bfloat16* __restrict__ sAlo,
    const __nv_bfloat16* __restrict__ sWhi, const __nv_bfloat16* __restrict__ sWlo,
    int tid)
{
    const int w = tid >> 5, lane = tid & 31;
    const int m0 = (w & 3) * 32;
    const int n0 = (w >> 2) * 32;

    #pragma unroll
    for (int i = 0; i < 32; i++) acc[i] = 0.f;

    const int arow = m0 + (lane & 15);
    const int akk  = (lane >> 4) << 3;
    uint32_t aAhi = (uint32_t)__cvta_generic_to_shared(sAhi + arow * AK + akk);
    uint32_t aAlo = (uint32_t)__cvta_generic_to_shared(sAlo + arow * AK + akk);
    const int brow = n0 + (lane & 7) + ((lane & 16) ? 8 : 0);
    const int bkk  = (lane & 8) ? 8 : 0;
    uint32_t aBhi = (uint32_t)__cvta_generic_to_shared(sWhi + brow * WK + bkk);
    uint32_t aBlo = (uint32_t)__cvta_generic_to_shared(sWlo + brow * WK + bkk);

    #pragma unroll
    for (int kb = 0; kb < 8; kb++) {
        uint32_t ah0[4], ah1[4], al0[4], al1[4];
        ldsm4(ah0, aAhi);
        ldsm4(ah1, aAhi + 16 * AK * 2);
        ldsm4(al0, aAlo);
        ldsm4(al1, aAlo + 16 * AK * 2);
        uint32_t bh0[4], bh1[4], bl0[4], bl1[4];
        ldsm4(bh0, aBhi);
        ldsm4(bh1, aBhi + 16 * WK * 2);
        ldsm4(bl0, aBlo);
        ldsm4(bl1, aBlo + 16 * WK * 2);

        #pragma unroll
        for (int mb = 0; mb < 2; mb++) {
            const uint32_t* ah = mb ? ah1 : ah0;
            const uint32_t* al = mb ? al1 : al0;
            #pragma unroll
            for (int nb = 0; nb < 4; nb++) {
                const uint32_t* bh = (nb < 2) ? bh0 : bh1;
                const uint32_t* bl = (nb < 2) ? bl0 : bl1;
                const int o = (nb & 1) * 2;
                float* c = acc + mb * 16 + nb * 4;
                mma16816(c, ah[0], ah[1], ah[2], ah[3], bh[o], bh[o+1]);
                mma16816(c, ah[0], ah[1], ah[2], ah[3], bl[o], bl[o+1]);
                mma16816(c, al[0], al[1], al[2], al[3], bh[o], bh[o+1]);
            }
        }
        aAhi += 32; aAlo += 32; aBhi += 32; aBlo += 32;   // 16 bf16 = 32 bytes
    }
}

// ============================================================
// Fused edge pass: 128 edges/tile, 512 threads
__global__ __launch_bounds__(ETHREADS, 1)
void edge_kernel(const float* __restrict__ u,
                 const float* __restrict__ v,
                 const float* __restrict__ edge_attr,
                 const float* __restrict__ W_e1, const float* __restrict__ b_e1,
                 const float* __restrict__ b_e2,
                 const float* __restrict__ b_c1,
                 const int*   __restrict__ edge_index)
{
    extern __shared__ __align__(16) char smem[];
    float* sIn  = (float*)(smem + OFF_UNION);      // GEMM1 inputs (phase 1)
    __nv_bfloat16* sClHi = (__nv_bfloat16*)(smem + OFF_UNION);               // [NCL][WK]
    __nv_bfloat16* sClLo = (__nv_bfloat16*)(smem + OFF_UNION + NCL*WK*2);
    int*   sRow = (int*)  (smem + OFF_ROW);
    float* sRad = (float*)(smem + OFF_RAD);
    __nv_bfloat16* sAhi = (__nv_bfloat16*)(smem + OFF_AHI);
    __nv_bfloat16* sAlo = (__nv_bfloat16*)(smem + OFF_ALO);
    __nv_bfloat16* sWhi = (__nv_bfloat16*)(smem + OFF_WHI);
    __nv_bfloat16* sWlo = (__nv_bfloat16*)(smem + OFF_WLO);
    float* sWF = (float*)(smem + OFF_WHI);         // fp32 [128][PF_STR] union view (PQ)

    const int tid = threadIdx.x;
    const int e0  = blockIdx.x * ETILE;

    // ---- setup: gather PQ as raw fp32 into W-region; w_diff; rad2 ----
    {   // gather P[row]+Q[col] -> fp32 (no splits)
        int e = tid >> 2, sub = tid & 3;
        int gidx = e0 + e;
        int r = edge_index[gidx];
        int c = edge_index[EE + gidx];
        const float4* Pr = (const float4*)(g_PQ + (size_t)r * 256);
        const float4* Qc = (const float4*)(g_PQ + (size_t)c * 256 + 128);
        float4* dst = (float4*)(sWF + e * PF_STR);
        #pragma unroll
        for (int i = 0; i < 8; i++) {
            int f4 = sub + 4*i;
            float4 a = Pr[f4];
            float4 b = Qc[f4];
            dst[f4] = make_float4(a.x+b.x, a.y+b.y, a.z+b.z, a.w+b.w);
        }
        if (sub == 0) {
            sRow[e] = r;
            sIn[e * SI_STR + 33] = edge_attr[gidx];
            sIn[e * SI_STR + 34] = 0.f;
            sIn[e * SI_STR + 35] = 0.f;
            atomicAdd(&g_cnt[r], 1.0f);
        }
    }

    for (int idx = tid; idx < ETILE * LVV; idx += ETHREADS) {   // w_diff
        int e = idx / LVV, lv = idx - e * LVV;
        int gidx = e0 + e;
        int r = edge_index[gidx], c = edge_index[EE + gidx];
        float ucv = u[c * LVV + lv], vcv = v[c * LVV + lv];
        float urv = u[r * LVV + lv], vrv = v[r * LVV + lv];
        float cs = sqrtf(ucv * ucv + vcv * vcv);
        float rs = sqrtf(urv * urv + vrv * vrv);
        float rd = (ucv * urv + vcv * vrv) / (cs * rs);
        float* rrow = sIn + e * SI_STR;
        rrow[0  + lv] = rd;
        rrow[11 + lv] = cs;
        rrow[22 + lv] = rs;
    }

    for (int e = tid; e < ETILE; e += ETHREADS) {               // rad2
        int gidx = e0 + e;
        int c = edge_index[EE + gidx];
        float su = 0.f, sv = 0.f;
        #pragma unroll
        for (int lv = 0; lv < LVV; lv++) {
            float a = u[c * LVV + lv], b = v[c * LVV + lv];
            su += a * a; sv += b * b;
        }
        sRad[e * 2 + 0] = sqrtf(su);
        sRad[e * 2 + 1] = sqrtf(sv);
    }
    __syncthreads();

    const int j  = tid & 127;
    const int eg = tid >> 7;       // 0..3, 32 rows each

    // ---- GEMM1 (34-k scalar): hid = relu(PQ + w_diff@W_e1[256:] + b_e1)
    //      reads fp32 PQ, writes hid bf16 splits into sA ----
    {
        const float* W1w = W_e1 + 256 * HH;
        float bb = b_e1[j];
        float acc[32];
        #pragma unroll
        for (int e = 0; e < 32; e++)
            acc[e] = sWF[(eg * 32 + e) * PF_STR + j] + bb;
        const float* base = sIn + (eg * 32) * SI_STR;
        for (int k = 0; k < 32; k += 4) {
            float w0 = W1w[(k+0)*HH + j], w1 = W1w[(k+1)*HH + j];
            float w2 = W1w[(k+2)*HH + j], w3 = W1w[(k+3)*HH + j];
            #pragma unroll
            for (int e = 0; e < 32; e++) {
                float4 a = *(const float4*)(base + e * SI_STR + k);
                acc[e] += a.x*w0 + a.y*w1 + a.z*w2 + a.w*w3;
            }
        }
        {
            float w0 = W1w[32*HH + j], w1 = W1w[33*HH + j];
            #pragma unroll
            for (int e = 0; e < 32; e++) {
                const float* rr = base + e * SI_STR;
                acc[e] += rr[32]*w0 + rr[33]*w1;
            }
        }
        #pragma unroll
        for (int e = 0; e < 32; e++) {
            float hv = fmaxf(acc[e], 0.f);
            __nv_bfloat16 hi, lo; bf16split(hv, hi, lo);
            int row = eg * 32 + e;
            sAhi[row * AK + j] = hi;
            sAlo[row * AK + j] = lo;
        }
    }
    __syncthreads();   // PQ fp32 + sIn dead; hid splits ready

    // ---- load We2 weights (overwrites PQ); stage Wcl splits (overwrites sIn) ----
    copy_weights(g_We2hi, g_We2lo, sWhi, sWlo, tid);
    {
        const uint4* s1 = (const uint4*)g_Wclhi;
        const uint4* s2 = (const uint4*)g_Wcllo;
        uint4* d1 = (uint4*)sClHi;
        uint4* d2 = (uint4*)sClLo;
        const int nv = NCL * WK * 2 / 16;   // 544
        for (int i = tid; i < nv; i += ETHREADS) { d1[i] = s1[i]; d2[i] = s2[i]; }
    }
    __syncthreads();

    // ---- GEMM2 (tensor): feat = relu(hid @ W_e2 + b_e2)
    //      epilogue: scatter to g_agg + write feat splits in place ----
    {
        float acc[32];
        mma_compute(acc, sAhi, sAlo, sWhi, sWlo, tid);
        __syncthreads();   // all MMA reads of sA (hid) / sW (We2) complete

        const int w = tid >> 5, lane = tid & 31;
        const int g = lane >> 2, tig = lane & 3;
        const int m0 = (w & 3) * 32;
        const int n0w = (w >> 2) * 32;
        #pragma unroll
        for (int mb = 0; mb < 2; mb++) {
            const int rA = m0 + mb * 16 + g;
            const int r0 = sRow[rA], r1 = sRow[rA + 8];
            #pragma unroll
            for (int nb = 0; nb < 4; nb++) {
                const int nn = n0w + nb * 8 + 2 * tig;
                const float* c = acc + mb * 16 + nb * 4;
                float b0 = b_e2[nn], b1 = b_e2[nn + 1];
                float v00 = fmaxf(c[0] + b0, 0.f);
                float v01 = fmaxf(c[1] + b1, 0.f);
                float v10 = fmaxf(c[2] + b0, 0.f);
                float v11 = fmaxf(c[3] + b1, 0.f);
                asm volatile("red.global.add.v2.f32 [%0], {%1,%2};"
                             :: "l"(g_agg + (size_t)r0 * HH + nn), "f"(v00), "f"(v01) : "memory");
                asm volatile("red.global.add.v2.f32 [%0], {%1,%2};"
                             :: "l"(g_agg + (size_t)r1 * HH + nn), "f"(v10), "f"(v11) : "memory");
                __nv_bfloat16 h0,l0,h1,l1;
                __nv_bfloat162 th, tl;
                bf16split(v00, h0, l0); bf16split(v01, h1, l1);
                th.x=h0; th.y=h1; tl.x=l0; tl.y=l1;
                *(__nv_bfloat162*)(sAhi + rA * AK + nn) = th;
                *(__nv_bfloat162*)(sAlo + rA * AK + nn) = tl;
                bf16split(v10, h0, l0); bf16split(v11, h1, l1);
                th.x=h0; th.y=h1; tl.x=l0; tl.y=l1;
                *(__nv_bfloat162*)(sAhi + (rA + 8) * AK + nn) = th;
                *(__nv_bfloat162*)(sAlo + (rA + 8) * AK + nn) = tl;
            }
        }
    }

    // ---- swap weights to W_c1 (We2 fully consumed before the sync above) ----
    copy_weights(g_Wc1hi, g_Wc1lo, sWhi, sWlo, tid);
    __syncthreads();

    // ---- coord GEMM1 (tensor): c1 = relu(feat @ W_c1 + b_c1),
    //      epilogue writes c1 bf16 splits back into sA ----
    {
        float acc[32];
        mma_compute(acc, sAhi, sAlo, sWhi, sWlo, tid);
        __syncthreads();   // all MMA reads of sA (feat) complete

        const int w = tid >> 5, lane = tid & 31;
        const int g = lane >> 2, tig = lane & 3;
        const int m0 = (w & 3) * 32;
        const int n0w = (w >> 2) * 32;
        #pragma unroll
        for (int mb = 0; mb < 2; mb++) {
            const int rA = m0 + mb * 16 + g;
            #pragma unroll
            for (int nb = 0; nb < 4; nb++) {
                const int nn = n0w + nb * 8 + 2 * tig;
                const float* c = acc + mb * 16 + nb * 4;
                float b0 = b_c1[nn], b1 = b_c1[nn + 1];
                float v00 = fmaxf(c[0] + b0, 0.f);
                float v01 = fmaxf(c[1] + b1, 0.f);
                float v10 = fmaxf(c[2] + b0, 0.f);
                float v11 = fmaxf(c[3] + b1, 0.f);
                __nv_bfloat16 h0,l0,h1,l1;
                __nv_bfloat162 th, tl;
                bf16split(v00, h0, l0); bf16split(v01, h1, l1);
                th.x=h0; th.y=h1; tl.x=l0; tl.y=l1;
                *(__nv_bfloat162*)(sAhi + rA * AK + nn) = th;
                *(__nv_bfloat162*)(sAlo + rA * AK + nn) = tl;
                bf16split(v10, h0, l0); bf16split(v11, h1, l1);
                th.x=h0; th.y=h1; tl.x=l0; tl.y=l1;
                *(__nv_bfloat162*)(sAhi + (rA + 8) * AK + nn) = th;
                *(__nv_bfloat162*)(sAlo + (rA + 8) * AK + nn) = tl;
            }
        }
    }
    __syncthreads();

    // ---- coord GEMM2 (tensor): wind = (c1 @ W_cl) * rad2, scatter to g_wind ----
    // 16 warps: warp w -> m-block (w&7)*16, n-half (w>>3)*16 (N padded to 32).
    {
        const int w = tid >> 5, lane = tid & 31;
        const int m0 = (w & 7) * 16;
        const int nh = (w >> 3) * 16;

        float acc[8];
        #pragma unroll
        for (int i = 0; i < 8; i++) acc[i] = 0.f;

        const int arow = m0 + (lane & 15);
        const int akk  = (lane >> 4) << 3;
        uint32_t aA = (uint32_t)__cvta_generic_to_shared(sAhi + arow * AK + akk);
        uint32_t aAl = (uint32_t)__cvta_generic_to_shared(sAlo + arow * AK + akk);
        const int brow = nh + (lane & 7) + ((lane & 16) ? 8 : 0);
        const int bkk  = (lane & 8) ? 8 : 0;
        uint32_t aB = (uint32_t)__cvta_generic_to_shared(sClHi + brow * WK + bkk);
        uint32_t aBl = (uint32_t)__cvta_generic_to_shared(sClLo + brow * WK + bkk);

        #pragma unroll
        for (int kb = 0; kb < 8; kb++) {
            uint32_t ah[4], al[4], bh[4], bl[4];
            ldsm4(ah, aA);
            ldsm4(al, aAl);
            ldsm4(bh, aB);
            ldsm4(bl, aBl);
            #pragma unroll
            for (int nb = 0; nb < 2; nb++) {
                const int o = nb * 2;
                float* c = acc + nb * 4;
                mma16816(c, ah[0], ah[1], ah[2], ah[3], bh[o], bh[o+1]);
                mma16816(c, ah[0], ah[1], ah[2], ah[3], bl[o], bl[o+1]);
                mma16816(c, al[0], al[1], al[2], al[3], bh[o], bh[o+1]);
            }
            aA += 32; aAl += 32; aB += 32; aBl += 32;
        }

        const int g = lane >> 2, tig = lane & 3;
        const int eA = m0 + g;
        const int r0 = sRow[eA], r1 = sRow[eA + 8];
        float ra0u = sRad[eA * 2], ra0v = sRad[eA * 2 + 1];
        float ra1u = sRad[(eA + 8) * 2], ra1v = sRad[(eA + 8) * 2 + 1];
        #pragma unroll
        for (int nb = 0; nb < 2; nb++) {
            const float* c = acc + nb * 4;
            #pragma unroll
            for (int q = 0; q < 2; q++) {
                int nn = nh + nb * 8 + 2 * tig + q;
                if (nn < 22) {
                    float r2a = (nn >= 11) ? ra0v : ra0u;
                    float r2b = (nn >= 11) ? ra1v : ra1u;
                    atomicAdd(&g_wind[(size_t)r0 * 22 + nn], c[q] * r2a);
                    atomicAdd(&g_wind[(size_t)r1 * 22 + nn], c[q + 2] * r2b);
                }
            }
        }
    }
}

// ============================================================
__global__ void lat_kernel() {
    int lt = blockIdx.x;
    int jj = threadIdx.x;
    float s = 0.f;
    for (int lon = 0; lon < NLON; lon++)
        s += g_agg[((size_t)lt * NLON + lon) * HH + jj];
    g_lat[lt * HH + jj] = s * (1.0f / NLON);
}

// ============================================================
__global__ __launch_bounds__(256, 3)
void node_kernel(const float* __restrict__ h,
                 const float* __restrict__ W_n1, const float* __restrict__ b_n1,
                 const float* __restrict__ W_n2, const float* __restrict__ b_n2,
                 float* __restrict__ out)
{
    extern __shared__ __align__(16) float smemf[];
    float* sA = smemf;
    float* sB = sA + NTILE * NA_STR;

    const int tid = threadIdx.x;
    const int n0  = blockIdx.x * NTILE;

    {
        int e = tid >> 3, sub = tid & 7;
        int n = n0 + e;
        float4* dst = (float4*)(sA + e * NA_STR);
        if (n < NN) {
            const float4* hh = (const float4*)(h + (size_t)n * HH);
            const float4* aa = (const float4*)(g_agg + (size_t)n * HH);
            const float4* ll = (const float4*)(g_lat + (size_t)(n / NLON) * HH);
            #pragma unroll
            for (int i = 0; i < 4; i++) {
                dst[sub + 8*i]      = hh[sub + 8*i];
                dst[32 + sub + 8*i] = aa[sub + 8*i];
                dst[64 + sub + 8*i] = ll[sub + 8*i];
            }
        } else {
            float4 z = make_float4(0.f, 0.f, 0.f, 0.f);
            #pragma unroll
            for (int i = 0; i < 4; i++) {
                dst[sub + 8*i] = z; dst[32 + sub + 8*i] = z; dst[64 + sub + 8*i] = z;
            }
        }
    }
    __syncthreads();

    const int j  = tid & 127;
    const int eg = tid >> 7;

    {
        u64 acc[16];
        #pragma unroll
        for (int e = 0; e < 16; e++) acc[e] = 0ULL;
        const float* base = sA + (eg * 16) * NA_STR;
        for (int k = 0; k < NA_STR; k += 4) {
            u64 W01 = pk2(W_n1[(k+0)*HH + j], W_n1[(k+1)*HH + j]);
            u64 W23 = pk2(W_n1[(k+2)*HH + j], W_n1[(k+3)*HH + j]);
            #pragma unroll
            for (int e = 0; e < 16; e++) {
                ulonglong2 a = *(const ulonglong2*)(base + e * NA_STR + k);
                ffma2(acc[e], a.x, W01);
                ffma2(acc[e], a.y, W23);
            }
        }
        float bb = b_n1[j];
        #pragma unroll
        for (int e = 0; e < 16; e++)
            sB[(eg*16 + e)*SB_STR + j] = fmaxf(hadd2(acc[e]) + bb, 0.f);
    }
    __syncthreads();

    {
        u64 acc[16];
        #pragma unroll
        for (int e = 0; e < 16; e++) acc[e] = 0ULL;
        const float* base = sB + (eg * 16) * SB_STR;
        for (int k = 0; k < 128; k += 4) {
            u64 W01 = pk2(W_n2[(k+0)*HH + j], W_n2[(k+1)*HH + j]);
            u64 W23 = pk2(W_n2[(k+2)*HH + j], W_n2[(k+3)*HH + j]);
            #pragma unroll
            for (int e = 0; e < 16; e++) {
                ulonglong2 a = *(const ulonglong2*)(base + e * SB_STR + k);
                ffma2(acc[e], a.x, W01);
                ffma2(acc[e], a.y, W23);
            }
        }
        float bb = b_n2[j];
        #pragma unroll
        for (int e = 0; e < 16; e++) {
            int n = n0 + eg*16 + e;
            if (n < NN)
                out[(size_t)n * HH + j] = hadd2(acc[e]) + bb + h[(size_t)n * HH + j];
        }
    }
}

// ============================================================
__global__ void coord_kernel(float* __restrict__ out) {
    int i = blockIdx.x * 256 + threadIdx.x;
    if (i >= NN * 22) return;
    int n = i / 22, m = i - n * 22;
    float cnt = fmaxf(g_cnt[n], 1.0f);
    float val = g_wind[i] / cnt;
    val = fminf(fmaxf(val, -100.0f), 100.0f);
    int lv = (m >= 11) ? (m - 11) : m;
    float* o = out + (size_t)NN * HH + (m >= 11 ? NN * LVV : 0) + n * LVV + lv;
    *o = val;
}

// ============================================================
extern "C" void kernel_launch(void* const* d_in, const int* in_sizes, int n_in,
                              void* d_out, int out_size)
{
    const float* h         = (const float*)d_in[0];
    const float* u         = (const float*)d_in[1];
    const float* v         = (const float*)d_in[2];
    const float* edge_attr = (const float*)d_in[3];
    const float* W_e1      = (const float*)d_in[4];
    const float* b_e1      = (const float*)d_in[5];
    const float* W_e2      = (const float*)d_in[6];
    const float* b_e2      = (const float*)d_in[7];
    const float* W_n1      = (const float*)d_in[8];
    const float* b_n1      = (const float*)d_in[9];
    const float* W_n2      = (const float*)d_in[10];
    const float* b_n2      = (const float*)d_in[11];
    const float* W_c1      = (const float*)d_in[12];
    const float* b_c1      = (const float*)d_in[13];
    const float* W_cl      = (const float*)d_in[14];
    const int*   edge_index= (const int*)  d_in[15];
    float* out = (float*)d_out;

    const int PQ_SMEM   = 64 * SB_STR * 4;
    const int NODE_SMEM = (NTILE * NA_STR + NTILE * SB_STR) * 4;
    cudaFuncSetAttribute(pq_kernel,   cudaFuncAttributeMaxDynamicSharedMemorySize, PQ_SMEM);
    cudaFuncSetAttribute(edge_kernel, cudaFuncAttributeMaxDynamicSharedMemorySize, EDGE_SMEM);
    cudaFuncSetAttribute(node_kernel, cudaFuncAttributeMaxDynamicSharedMemorySize, NODE_SMEM);

    zero_kernel<<<(NN * HH + 255) / 256, 256>>>();
    wsplit_kernel<<<(2 * HH * HH + NCL * HH + 255) / 256, 256>>>(W_e2, W_c1, W_cl);

    pq_kernel<<<(NN + 63) / 64, 256, PQ_SMEM>>>(h, W_e1);

    edge_kernel<<<EE / ETILE, ETHREADS, EDGE_SMEM>>>(u, v, edge_attr,
                                                     W_e1, b_e1, b_e2,
                                                     b_c1, edge_index);

    lat_kernel<<<NLAT, HH>>>();

    node_kernel<<<(NN + NTILE - 1) / NTILE, 256, NODE_SMEM>>>(h, W_n1, b_n1, W_n2, b_n2, out);

    coord_kernel<<<(NN * 22 + 255) / 256, 256>>>(out);
}